// round 16
// baseline (speedup 1.0000x reference)
#include <cuda_runtime.h>
#include <cstdint>

// ---------------- problem constants ----------------
#define R    2048   // reservoir
#define Bz   16     // batch
#define Tn   2048   // timesteps
#define NO   3      // output size
#define KSTORE 320  // CSR storage per row (8.4 sigma above mean nnz; empirically safe)
#define KIT  26     // main-loop iterations (208 slots), register-hoisted, all warps
#define KEXT 14     // max conditional extra iterations (slots 208..319), register-hoisted
#define NBLK 148    // persistent blocks (<= SM count on B300/GB300)
#define WPB  14     // rows per block, one warp per row -> 148*14 = 2072 >= 2048
#define TPB  (WPB * 32)

// ---------------- device scratch (static; no runtime alloc) ----------------
__device__ uint2    g_pairs[(size_t)R * KSTORE];        // (col, val-bits), zero-padded to KSTORE
__device__ int      g_ext[R];                           // ceil((nnz-208)/8), clamped to [0,14]
__device__ float    g_hs[(size_t)(Tn + 1) * R * Bz];    // fp32 state history [t][col][b]
__device__ unsigned g_count;                            // barrier arrival counter
                                                        // (reset by build_csr each replay)

// ---------------- kernel 1: build padded CSR + reset counter + zero h0 ----------------
__global__ void build_csr(const float* __restrict__ W) {
    if (blockIdx.x == 0 && threadIdx.x == 0) g_count = 0u;

    int warp = (blockIdx.x * blockDim.x + threadIdx.x) >> 5;
    int lane = threadIdx.x & 31;
    if (warp >= R) return;
    const int r = warp;
    const float* wrow = W + (size_t)r * R;
    uint2* prow = g_pairs + (size_t)r * KSTORE;

    int base = 0;
    for (int c0 = 0; c0 < R; c0 += 32) {
        float w = wrow[c0 + lane];
        unsigned m = __ballot_sync(0xffffffffu, w != 0.0f);
        if (w != 0.0f) {
            int pos = base + __popc(m & ((1u << lane) - 1u));
            if (pos < KSTORE)
                prow[pos] = make_uint2((unsigned)(c0 + lane), __float_as_uint(w));
        }
        base += __popc(m);
    }
    if (base > KSTORE) base = KSTORE;
    // zero-fill the rest of the row's storage (val 0 -> harmless FMA on col 0)
    for (int p = base + lane; p < KSTORE; p += 32)
        prow[p] = make_uint2(0u, 0u);
    if (lane == 0) {
        int e = (base > KIT * 8) ? ((base - KIT * 8 + 7) >> 3) : 0;
        g_ext[r] = (e > KEXT) ? KEXT : e;
    }
    if (lane < Bz) g_hs[(size_t)r * Bz + lane] = 0.0f;
}

// ---------------- fast tanh (abs err ~1e-6, clamped) ----------------
__device__ __forceinline__ float tanh_fast(float v) {
    v = fminf(fmaxf(v, -12.0f), 12.0f);
    float e = __expf(2.0f * v);
    return __fdividef(e - 1.0f, e + 1.0f);
}

// ---------------- kernel 2: persistent recurrence (R15 core + per-row adaptive gather) ----------------
// One warp per row. lane = s (k-slice 0..7) x bq (batch-quad 0..3).
// Main loop: 26 register-resident LDG.128 gathers (slots 0..207) -- below mean nnz.
// Extra: up to 14 single conditional iterations (slots 208..319), register-hoisted
// with compile-time indices and a runtime warp-uniform predicate k < ext.
// Average executed iterations ~26.6 vs 32.04 in R15 (-17% gather work).
// Barrier: single global counter, 1 REDG arrival/block, 1 poller lane (proven R14).
__global__ __launch_bounds__(TPB, 1) void esn_steps(const float* __restrict__ x,
                                                    const float* __restrict__ Win) {
    __shared__ float xs[2][Bz * 3];

    const int tid  = threadIdx.x;
    const int w    = tid >> 5;
    const int lane = tid & 31;
    const int s    = lane >> 2;
    const int bq   = lane & 3;
    const int r    = blockIdx.x * WPB + w;
    const bool active = (r < R);

    // hoist this lane's k-slice streams into registers (main + extra)
    unsigned off[KIT];
    float    val[KIT];
    unsigned off2[KEXT];
    float    val2[KEXT];
    int ext = 0;
    float w0 = 0.f, w1 = 0.f, w2 = 0.f;
    if (active) {
        w0 = Win[r * 3 + 0];
        w1 = Win[r * 3 + 1];
        w2 = Win[r * 3 + 2];
        ext = g_ext[r];
        const uint2* p = g_pairs + (size_t)r * KSTORE + s;
        #pragma unroll
        for (int k = 0; k < KIT; ++k) {
            uint2 pr = __ldg(p + (k << 3));
            off[k] = pr.x * (Bz * 4) + bq * 16;
            val[k] = __uint_as_float(pr.y);
        }
        #pragma unroll
        for (int k = 0; k < KEXT; ++k) {         // slots 208..319, zero-padded
            uint2 pr = __ldg(p + ((KIT + k) << 3));
            off2[k] = pr.x * (Bz * 4) + bq * 16;
            val2[k] = __uint_as_float(pr.y);
        }
    } else {
        #pragma unroll
        for (int k = 0; k < KIT; ++k) { off[k] = (unsigned)(bq * 16); val[k] = 0.f; }
        #pragma unroll
        for (int k = 0; k < KEXT; ++k) { off2[k] = (unsigned)(bq * 16); val2[k] = 0.f; }
    }

    for (int t = 0; t < Tn; ++t) {
        // stage x[:, t, :] (48 floats) — independent of h, overlaps the poll
        if (tid < Bz * 3) {
            int b = tid / 3, i = tid - b * 3;
            xs[t & 1][tid] = x[((size_t)b * Tn + t) * 3 + i];
        }
        // wait until all 148 blocks have published step t-1: count >= 148*t
        if (t > 0 && tid == 0) {
            const unsigned tgt = (unsigned)(NBLK * t);
            for (;;) {
                unsigned c;
                asm volatile("ld.acquire.gpu.global.b32 %0,[%1];" : "=r"(c) : "l"(&g_count));
                if (c >= tgt) break;
            }
        }
        __syncthreads();

        // main gather + FMA: 26 independent LDG.128 (register-resident addresses)
        const char* hb = (const char*)g_hs + (size_t)t * (R * Bz * 4);
        float4 acc = make_float4(0.f, 0.f, 0.f, 0.f);
        #pragma unroll
        for (int k = 0; k < KIT; ++k) {
            float4 hv = __ldg((const float4*)(hb + off[k]));
            acc.x = fmaf(val[k], hv.x, acc.x);
            acc.y = fmaf(val[k], hv.y, acc.y);
            acc.z = fmaf(val[k], hv.z, acc.z);
            acc.w = fmaf(val[k], hv.w, acc.w);
        }
        // extra iterations: warp-uniform predicate, compile-time register indices
        #pragma unroll
        for (int k = 0; k < KEXT; ++k) {
            if (k < ext) {
                float4 hv = __ldg((const float4*)(hb + off2[k]));
                acc.x = fmaf(val2[k], hv.x, acc.x);
                acc.y = fmaf(val2[k], hv.y, acc.y);
                acc.z = fmaf(val2[k], hv.z, acc.z);
                acc.w = fmaf(val2[k], hv.w, acc.w);
            }
        }
        // reduce across the 8 k-slices; after 3 rounds ALL lanes hold full sums
        #pragma unroll
        for (int o = 16; o >= 4; o >>= 1) {
            acc.x += __shfl_xor_sync(0xffffffffu, acc.x, o);
            acc.y += __shfl_xor_sync(0xffffffffu, acc.y, o);
            acc.z += __shfl_xor_sync(0xffffffffu, acc.z, o);
            acc.w += __shfl_xor_sync(0xffffffffu, acc.w, o);
        }
        // widened epilogue: 16 lanes (s<4) each finish ONE batch b = bq*4+s
        if (active && s < 4) {
            float v = (s == 0) ? acc.x : (s == 1) ? acc.y : (s == 2) ? acc.z : acc.w;
            const int b = bq * 4 + s;
            const float* xc = xs[t & 1];
            float o = tanh_fast(v + xc[b*3]*w0 + xc[b*3+1]*w1 + xc[b*3+2]*w2);
            g_hs[(size_t)(t + 1) * (R * Bz) + (size_t)r * Bz + b] = o;   // one 64B line/row
        }
        // publish this block's h[t+1] writes: release-ordered increment
        __syncthreads();
        if (tid == 0)
            asm volatile("red.release.gpu.global.add.u32 [%0], %1;"
                         :: "l"(&g_count), "r"(1u) : "memory");
    }
}

// ---------------- kernel 3: out[b][t][o] = hs[t+1] . Wout[o] + bias[o] ----------------
__global__ void esn_out(const float* __restrict__ Wout_w,
                        const float* __restrict__ Wout_b,
                        float* __restrict__ out) {
    const int t   = blockIdx.x;
    const int tid = threadIdx.x;
    const float* h = g_hs + (size_t)(t + 1) * R * Bz;

    const int b = tid & 15;
    const int g = tid >> 4;
    float a0 = 0.f, a1 = 0.f, a2 = 0.f;
    for (int r = g; r < R; r += 16) {
        float hv = __ldg(h + (size_t)r * Bz + b);
        a0 = fmaf(hv, __ldg(Wout_w + r),         a0);
        a1 = fmaf(hv, __ldg(Wout_w + R + r),     a1);
        a2 = fmaf(hv, __ldg(Wout_w + 2 * R + r), a2);
    }
    __shared__ float red[256][3];
    red[tid][0] = a0; red[tid][1] = a1; red[tid][2] = a2;
    __syncthreads();
    if (tid < Bz * NO) {
        int bb = tid / 3, o = tid - bb * 3;
        float sum = 0.f;
        #pragma unroll
        for (int gg = 0; gg < 16; ++gg) sum += red[gg * 16 + bb][o];
        out[((size_t)bb * Tn + t) * 3 + o] = sum + Wout_b[o];
    }
}

// ---------------- launch ----------------
extern "C" void kernel_launch(void* const* d_in, const int* in_sizes, int n_in,
                              void* d_out, int out_size) {
    const float* x      = (const float*)d_in[0];  // [16, 2048, 3]
    const float* Win    = (const float*)d_in[1];  // [2048, 3]
    const float* W      = (const float*)d_in[2];  // [2048, 2048]
    const float* Wout_w = (const float*)d_in[3];  // [3, 2048]
    const float* Wout_b = (const float*)d_in[4];  // [3]
    float* out = (float*)d_out;                   // [16, 2048, 3]

    (void)in_sizes; (void)n_in; (void)out_size;

    build_csr<<<(R * 32 + 255) / 256, 256>>>(W);   // CSR + counter/h0 reset
    esn_steps<<<NBLK, TPB>>>(x, Win);              // 2048 steps, per-row adaptive gather
    esn_out<<<Tn, 256>>>(Wout_w, Wout_b, out);     // readout projection
}